// round 13
// baseline (speedup 1.0000x reference)
#include <cuda_runtime.h>
#include <cuda_fp16.h>
#include <cuda_fp8.h>
#include <cstdint>
#include <float.h>

#define PQ     8191
#define NDIM   1024
#define LDS    8192
#define MARGIN 30.0f
#define MAXSEL 2048

// ---------------- scratch (static device memory, no allocation) ------------
__device__ __half  g_S [(size_t)LDS * LDS];     // 8192x8192 fp16 approx logits
__device__ uint8_t g_s8[(size_t)8192 * 1024];   // s in e4m3 (row 8191 zero)
__device__ uint8_t g_x8[(size_t)8192 * 1024];   // X in e4m3

// ---------------- helpers ---------------------------------------------------
__device__ __forceinline__ uint32_t smem_to_u32(const void* p) {
    uint32_t a;
    asm("{ .reg .u64 t; cvta.to.shared.u64 t, %1; cvt.u32.u64 %0, t; }" : "=r"(a) : "l"(p));
    return a;
}
__device__ __forceinline__ void cp16(uint32_t s, const void* g) {
    asm volatile("cp.async.cg.shared.global [%0], [%1], 16;" :: "r"(s), "l"(g));
}
#define CP_COMMIT() asm volatile("cp.async.commit_group;" ::: "memory")
#define CP_WAIT1()  asm volatile("cp.async.wait_group 1;" ::: "memory")

#define LDSM_X4(R, ADDR) \
    asm volatile("ldmatrix.sync.aligned.m8n8.x4.shared.b16 {%0,%1,%2,%3}, [%4];" \
        : "=r"((R)[0]), "=r"((R)[1]), "=r"((R)[2]), "=r"((R)[3]) : "r"(ADDR))
#define LDSM_X2(R, ADDR) \
    asm volatile("ldmatrix.sync.aligned.m8n8.x2.shared.b16 {%0,%1}, [%2];" \
        : "=r"((R)[0]), "=r"((R)[1]) : "r"(ADDR))
// fp8 e4m3 MMA: 16x8x32, fragment byte-layout identical to fp16 m16n8k16
#define MMAF8(D, A, B) \
    asm volatile("mma.sync.aligned.m16n8k32.row.col.f32.e4m3.e4m3.f32 " \
        "{%0,%1,%2,%3}, {%4,%5,%6,%7}, {%8,%9}, {%0,%1,%2,%3};" \
        : "+f"((D)[0]), "+f"((D)[1]), "+f"((D)[2]), "+f"((D)[3]) \
        : "r"((A)[0]), "r"((A)[1]), "r"((A)[2]), "r"((A)[3]), "r"((B)[0]), "r"((B)[1]))

// ---------------- prep: fp32 -> e4m3 ---------------------------------------
__global__ void cvt_fp8(const float* __restrict__ src, uint8_t* __restrict__ dst,
                        size_t nvalid) {
    size_t i = ((size_t)blockIdx.x * blockDim.x + threadIdx.x) * 4;
    uchar4 o;
    float4 v = make_float4(0.f, 0.f, 0.f, 0.f);
    if (i + 3 < nvalid) v = *(const float4*)(src + i);
    else {
        if (i + 0 < nvalid) v.x = src[i + 0];
        if (i + 1 < nvalid) v.y = src[i + 1];
        if (i + 2 < nvalid) v.z = src[i + 2];
        if (i + 3 < nvalid) v.w = src[i + 3];
    }
    o.x = (uint8_t)__nv_cvt_float_to_fp8(v.x, __NV_SATFINITE, __NV_E4M3);
    o.y = (uint8_t)__nv_cvt_float_to_fp8(v.y, __NV_SATFINITE, __NV_E4M3);
    o.z = (uint8_t)__nv_cvt_float_to_fp8(v.z, __NV_SATFINITE, __NV_E4M3);
    o.w = (uint8_t)__nv_cvt_float_to_fp8(v.w, __NV_SATFINITE, __NV_E4M3);
    *(uchar4*)(dst + i) = o;
}

// ---------------- Phase A: fp8 QK screening GEMM ---------------------------
// S[128*by][128*bx] = s8 @ x8^T (approx logits, fp16 out).
// BM=BN=128, BK=64 (2 k-slabs of 32), 128 threads (2x2 warps, 64x64 warp
// tile), 2-stage cp.async pipeline, 80B padded rows, 2 CTAs/SM.
#define ROWB   80                        // 64 B data + 16 B pad
#define MATB   (128 * ROWB)              // 10240 B
#define STAGEB (2 * MATB)                // A | B
#define GSMEM  (2 * STAGEB)              // 40960 B

__global__ __launch_bounds__(128, 2) void qk_gemm(
        const uint8_t* __restrict__ A8, const uint8_t* __restrict__ B8) {
    extern __shared__ char sm[];
    const uint32_t smb = smem_to_u32(sm);
    const int tid = threadIdx.x, lane = tid & 31, wid = tid >> 5;
    const int wm = wid & 1, wn = wid >> 1;
    const size_t arow0 = (size_t)blockIdx.y * 128;
    const size_t brow0 = (size_t)blockIdx.x * 128;

    float acc[4][8][4];
#pragma unroll
    for (int a = 0; a < 4; a++)
#pragma unroll
        for (int b = 0; b < 8; b++)
#pragma unroll
            for (int c = 0; c < 4; c++) acc[a][b][c] = 0.f;

    auto load_stage = [&](int stg, int k0) {
        const uint32_t base = smb + stg * STAGEB;
#pragma unroll
        for (int c = tid; c < 512; c += 128) {        // 128 rows x 4 16B-chunks
            const int row = c >> 2, kc = c & 3;
            const uint32_t so = base + row * ROWB + kc * 16;
            cp16(so,        A8 + (arow0 + row) * NDIM + k0 + kc * 16);
            cp16(so + MATB, B8 + (brow0 + row) * NDIM + k0 + kc * 16);
        }
    };

    const int nk = NDIM / 64;                          // 16 iterations
    load_stage(0, 0);  CP_COMMIT();
    load_stage(1, 64); CP_COMMIT();

    for (int it = 0; it < nk; ++it) {
        CP_WAIT1();
        __syncthreads();

        const uint32_t base = smb + (it & 1) * STAGEB;
#pragma unroll
        for (int ks = 0; ks < 2; ks++) {               // two K=32 slabs
            const uint32_t a_off = (uint32_t)((wm * 64 + (lane & 15)) * ROWB + ks * 32 + (lane >> 4) * 16);
            const uint32_t b_off = (uint32_t)((wn * 64 + (lane & 7)) * ROWB + ks * 32 + ((lane >> 3) & 1) * 16);
            uint32_t fa[4][4], fb[8][2];
#pragma unroll
            for (int mi = 0; mi < 4; mi++) LDSM_X4(fa[mi], base + a_off + mi * 16 * ROWB);
#pragma unroll
            for (int ni = 0; ni < 8; ni++) LDSM_X2(fb[ni], base + MATB + b_off + ni * 8 * ROWB);
#pragma unroll
            for (int mi = 0; mi < 4; mi++)
#pragma unroll
                for (int ni = 0; ni < 8; ni++) MMAF8(acc[mi][ni], fa[mi], fb[ni]);
        }
        __syncthreads();

        if (it + 2 < nk) load_stage(it & 1, (it + 2) * 64);
        CP_COMMIT();
    }

    // epilogue: fp16 stores
#pragma unroll
    for (int mi = 0; mi < 4; mi++) {
        const size_t q0 = arow0 + wm * 64 + mi * 16 + (lane >> 2);
        const size_t q1 = q0 + 8;
#pragma unroll
        for (int ni = 0; ni < 8; ni++) {
            const size_t col = brow0 + wn * 64 + ni * 8 + (lane & 3) * 2;
            *(__half2*)&g_S[q0 * LDS + col] = __floats2half2_rn(acc[mi][ni][0], acc[mi][ni][1]);
            *(__half2*)&g_S[q1 * LDS + col] = __floats2half2_rn(acc[mi][ni][2], acc[mi][ni][3]);
        }
    }
}

// ---------------- Phase B: select + exact softmax + sparse PV --------------
// One block per query row. S row staged in smem once; approx max + candidate
// selection from smem; selected logits recomputed exactly in fp32; softmax;
// out[q] = sum p_k * X[k+1].
__global__ __launch_bounds__(256) void sparse_out(const float* __restrict__ X,
                                                  const float* __restrict__ s,
                                                  float* __restrict__ out) {
    __shared__ float  s_srow[NDIM];
    __shared__ __half s_row[LDS];
    __shared__ int    s_idx[MAXSEL];
    __shared__ float  s_val[MAXSEL];
    __shared__ float  s_red[8];
    __shared__ int    s_cnt;
    __shared__ float  s_bcast[2];

    const int q = blockIdx.x;
    const int tid = threadIdx.x, lane = tid & 31, wid = tid >> 5;

    // stage S row (16 KB) + s row (4 KB) into smem, vectorized
    const uint4* Sr4 = (const uint4*)(g_S + (size_t)q * LDS);
    for (int i = tid; i < LDS / 8; i += 256) ((uint4*)s_row)[i] = Sr4[i];
    const float4* srow4 = (const float4*)(s + (size_t)q * NDIM);
    for (int i = tid; i < NDIM / 4; i += 256) ((float4*)s_srow)[i] = srow4[i];
    if (tid == 0) s_cnt = 0;
    __syncthreads();
    if (tid == 0) s_row[PQ] = __ushort_as_half(0xFC00);   // -inf: kill pad key
    __syncthreads();

    // pass 1: approx row max over smem (half2)
    const __half2* r2 = (const __half2*)s_row;
    __half2 m2 = __halves2half2(__ushort_as_half(0xFC00), __ushort_as_half(0xFC00));
    for (int i = tid; i < LDS / 2; i += 256) m2 = __hmax2(m2, r2[i]);
    float lmax = fmaxf(__low2float(m2), __high2float(m2));
#pragma unroll
    for (int o = 16; o; o >>= 1) lmax = fmaxf(lmax, __shfl_xor_sync(0xffffffffu, lmax, o));
    if (lane == 0) s_red[wid] = lmax;
    __syncthreads();
    if (tid == 0) {
        float m = s_red[0];
#pragma unroll
        for (int w = 1; w < 8; w++) m = fmaxf(m, s_red[w]);
        s_bcast[0] = m;
    }
    __syncthreads();
    const float thr = s_bcast[0] - MARGIN;

    // pass 2: select candidates from smem
    for (int i = tid; i < LDS / 2; i += 256) {
        __half2 v = r2[i];
        if (__low2float(v) >= thr) {
            int p = atomicAdd(&s_cnt, 1);
            if (p < MAXSEL) s_idx[p] = 2 * i;
        }
        if (__high2float(v) >= thr) {
            int p = atomicAdd(&s_cnt, 1);
            if (p < MAXSEL) s_idx[p] = 2 * i + 1;
        }
    }
    __syncthreads();
    const int cnt = min(s_cnt, MAXSEL);

    // exact fp32 logits for selected keys: one warp per key
    for (int j = wid; j < cnt; j += 8) {
        const float* xr = X + (size_t)s_idx[j] * NDIM;
        float a = 0.f;
        for (int i = lane; i < NDIM; i += 32) a += s_srow[i] * xr[i];
#pragma unroll
        for (int o = 16; o; o >>= 1) a += __shfl_xor_sync(0xffffffffu, a, o);
        if (lane == 0) s_val[j] = a;
    }
    __syncthreads();

    // softmax over the cnt exact logits (warp 0)
    if (wid == 0) {
        float m = -FLT_MAX;
        for (int j = lane; j < cnt; j += 32) m = fmaxf(m, s_val[j]);
#pragma unroll
        for (int o = 16; o; o >>= 1) m = fmaxf(m, __shfl_xor_sync(0xffffffffu, m, o));
        float sum = 0.f;
        for (int j = lane; j < cnt; j += 32) {
            float e = __expf(s_val[j] - m);
            s_val[j] = e;
            sum += e;
        }
#pragma unroll
        for (int o = 16; o; o >>= 1) sum += __shfl_xor_sync(0xffffffffu, sum, o);
        if (lane == 0) s_bcast[1] = 1.f / sum;
    }
    __syncthreads();
    const float inv = s_bcast[1];

    // out[q] = sum_j p_j * X[idx_j + 1]; 256 threads x float4
    float4 o = make_float4(0.f, 0.f, 0.f, 0.f);
    for (int j = 0; j < cnt; j++) {
        const float p = s_val[j] * inv;
        const float4 v = ((const float4*)(X + (size_t)(s_idx[j] + 1) * NDIM))[tid];
        o.x += p * v.x; o.y += p * v.y; o.z += p * v.z; o.w += p * v.w;
    }
    ((float4*)(out + (size_t)q * NDIM))[tid] = o;
}

// ---------------- launcher -------------------------------------------------
extern "C" void kernel_launch(void* const* d_in, const int* in_sizes, int n_in,
                              void* d_out, int out_size) {
    const float* X = (const float*)d_in[0];   // (8192, 1024)
    const float* s = (const float*)d_in[1];   // (8191, 1024)
    float* out = (float*)d_out;               // (8191, 1024)

    static bool attr_set = false;
    if (!attr_set) {
        cudaFuncSetAttribute(qk_gemm, cudaFuncAttributeMaxDynamicSharedMemorySize, GSMEM);
        attr_set = true;
    }

    void *p_s8, *p_x8;
    cudaGetSymbolAddress(&p_s8, g_s8);
    cudaGetSymbolAddress(&p_x8, g_x8);

    const size_t NE = (size_t)8192 * 1024;

    cvt_fp8<<<NE / 4 / 256, 256>>>(s, (uint8_t*)p_s8, (size_t)PQ * NDIM);
    cvt_fp8<<<NE / 4 / 256, 256>>>(X, (uint8_t*)p_x8, NE);

    // Phase A: approx logits S = s @ X^T  (e4m3 in, fp16 out)
    qk_gemm<<<dim3(64, 64), 128, GSMEM>>>((const uint8_t*)p_s8, (const uint8_t*)p_x8);

    // Phase B: select + exact softmax + sparse PV
    sparse_out<<<PQ, 256>>>(X, s, out);
}

// round 16
// speedup vs baseline: 1.1034x; 1.1034x over previous
#include <cuda_runtime.h>
#include <cuda_fp16.h>
#include <cstdint>
#include <float.h>

#define PQ     8191
#define NDIM   1024
#define LDS    8192
#define MARGIN 25.0f
#define MAXSEL 2048

// ---------------- scratch (static device memory, no allocation) ------------
__device__ __half   g_S [(size_t)LDS * LDS];    // 8192x8192 fp16 approx logits
__device__ __half   g_sh[(size_t)8192 * 1024];  // s in fp16 (row 8191 zero)
__device__ __half   g_xh[(size_t)8192 * 1024];  // X in fp16
__device__ unsigned g_rowmax[LDS];              // per-row max, monotonic encoding

// monotonic float<->unsigned ordering encode/decode
__device__ __forceinline__ unsigned enc_f(float f) {
    unsigned u = __float_as_uint(f);
    return (u & 0x80000000u) ? ~u : (u | 0x80000000u);
}
__device__ __forceinline__ float dec_f(unsigned u) {
    return __uint_as_float((u & 0x80000000u) ? (u ^ 0x80000000u) : ~u);
}

// ---------------- helpers ---------------------------------------------------
__device__ __forceinline__ uint32_t smem_to_u32(const void* p) {
    uint32_t a;
    asm("{ .reg .u64 t; cvta.to.shared.u64 t, %1; cvt.u32.u64 %0, t; }" : "=r"(a) : "l"(p));
    return a;
}
__device__ __forceinline__ void cp16(uint32_t s, const void* g) {
    asm volatile("cp.async.cg.shared.global [%0], [%1], 16;" :: "r"(s), "l"(g));
}
#define CP_COMMIT() asm volatile("cp.async.commit_group;" ::: "memory")
#define CP_WAIT1()  asm volatile("cp.async.wait_group 1;" ::: "memory")

#define LDSM_X4(R, ADDR) \
    asm volatile("ldmatrix.sync.aligned.m8n8.x4.shared.b16 {%0,%1,%2,%3}, [%4];" \
        : "=r"((R)[0]), "=r"((R)[1]), "=r"((R)[2]), "=r"((R)[3]) : "r"(ADDR))
#define LDSM_X2(R, ADDR) \
    asm volatile("ldmatrix.sync.aligned.m8n8.x2.shared.b16 {%0,%1}, [%2];" \
        : "=r"((R)[0]), "=r"((R)[1]) : "r"(ADDR))
#define MMA16816(D, A, B) \
    asm volatile("mma.sync.aligned.m16n8k16.row.col.f32.f16.f16.f32 " \
        "{%0,%1,%2,%3}, {%4,%5,%6,%7}, {%8,%9}, {%0,%1,%2,%3};" \
        : "+f"((D)[0]), "+f"((D)[1]), "+f"((D)[2]), "+f"((D)[3]) \
        : "r"((A)[0]), "r"((A)[1]), "r"((A)[2]), "r"((A)[3]), "r"((B)[0]), "r"((B)[1]))

// ---------------- prep ------------------------------------------------------
__global__ void cvt_half(const float* __restrict__ src, __half* __restrict__ dst,
                         size_t nvalid) {
    size_t i = (size_t)blockIdx.x * blockDim.x + threadIdx.x;
    float v = (i < nvalid) ? src[i] : 0.f;
    dst[i] = __float2half(v);
}

__global__ void init_rowmax() {
    g_rowmax[blockIdx.x * 256 + threadIdx.x] = 0u;   // encodes -inf side
}

// ---------------- Phase A: fp16 QK screening GEMM + row-max epilogue -------
// S[128*by][128*bx] = sh @ xh^T (fp16 out). BM=BN=128, BK=32, 128 threads
// (2x2 warps, warp tile 64x64), 2-stage cp.async, 80B rows, 2 CTAs/SM.
#define ROWB   80
#define MATB   (128 * ROWB)              // 10240 B
#define STAGEB (2 * MATB)
#define GSMEM  (2 * STAGEB)              // 40960 B

__global__ __launch_bounds__(128, 2) void qk_gemm(
        const __half* __restrict__ Ah, const __half* __restrict__ Bh) {
    extern __shared__ char sm[];
    const uint32_t smb = smem_to_u32(sm);
    const int tid = threadIdx.x, lane = tid & 31, wid = tid >> 5;
    const int wm = wid & 1, wn = wid >> 1;
    const size_t arow0 = (size_t)blockIdx.y * 128;
    const size_t brow0 = (size_t)blockIdx.x * 128;

    float acc[4][8][4];
#pragma unroll
    for (int a = 0; a < 4; a++)
#pragma unroll
        for (int b = 0; b < 8; b++)
#pragma unroll
            for (int c = 0; c < 4; c++) acc[a][b][c] = 0.f;

    auto load_stage = [&](int stg, int k0) {
        const uint32_t base = smb + stg * STAGEB;
#pragma unroll
        for (int c = tid; c < 512; c += 128) {
            const int row = c >> 2, kc = c & 3;
            const uint32_t so = base + row * ROWB + kc * 16;
            cp16(so,        Ah + (arow0 + row) * NDIM + k0 + kc * 8);
            cp16(so + MATB, Bh + (brow0 + row) * NDIM + k0 + kc * 8);
        }
    };

    const int nk = NDIM / 32;
    load_stage(0, 0);  CP_COMMIT();
    load_stage(1, 32); CP_COMMIT();

    for (int it = 0; it < nk; ++it) {
        CP_WAIT1();
        __syncthreads();

        const uint32_t base = smb + (it & 1) * STAGEB;
#pragma unroll
        for (int ks = 0; ks < 2; ks++) {
            const int k0 = ks * 16;
            const uint32_t a_off = (uint32_t)((wm * 64 + (lane & 15)) * ROWB + (k0 + (lane >> 4) * 8) * 2);
            const uint32_t b_off = (uint32_t)((wn * 64 + (lane & 7)) * ROWB + (k0 + ((lane >> 3) & 1) * 8) * 2);
            uint32_t fa[4][4], fb[8][2];
#pragma unroll
            for (int mi = 0; mi < 4; mi++) LDSM_X4(fa[mi], base + a_off + mi * 16 * ROWB);
#pragma unroll
            for (int ni = 0; ni < 8; ni++) LDSM_X2(fb[ni], base + MATB + b_off + ni * 8 * ROWB);
#pragma unroll
            for (int mi = 0; mi < 4; mi++)
#pragma unroll
                for (int ni = 0; ni < 8; ni++) MMA16816(acc[mi][ni], fa[mi], fb[ni]);
        }
        __syncthreads();

        if (it + 2 < nk) load_stage(it & 1, (it + 2) * 32);
        CP_COMMIT();
    }

    // column of the first element this thread owns within its 8-col fragment
    const int col_base = (int)brow0 + wn * 64 + (lane & 3) * 2;

    // epilogue: fp16 stores + per-row max -> atomicMax
#pragma unroll
    for (int mi = 0; mi < 4; mi++) {
        const size_t q0 = arow0 + wm * 64 + mi * 16 + (lane >> 2);
        const size_t q1 = q0 + 8;
        float m0 = -FLT_MAX, m1 = -FLT_MAX;
#pragma unroll
        for (int ni = 0; ni < 8; ni++) {
            const size_t col = brow0 + wn * 64 + ni * 8 + (lane & 3) * 2;
            *(__half2*)&g_S[q0 * LDS + col] = __floats2half2_rn(acc[mi][ni][0], acc[mi][ni][1]);
            *(__half2*)&g_S[q1 * LDS + col] = __floats2half2_rn(acc[mi][ni][2], acc[mi][ni][3]);
            // invalid key 8191 can only be the +1 element of ni==7 on the last tile
            const bool last_valid = (col_base + ni * 8 + 1) < PQ;
            m0 = fmaxf(m0, fmaxf(acc[mi][ni][0], last_valid ? acc[mi][ni][1] : -FLT_MAX));
            m1 = fmaxf(m1, fmaxf(acc[mi][ni][2], last_valid ? acc[mi][ni][3] : -FLT_MAX));
        }
        // reduce across the 4-lane column group
        m0 = fmaxf(m0, __shfl_xor_sync(0xffffffffu, m0, 1));
        m0 = fmaxf(m0, __shfl_xor_sync(0xffffffffu, m0, 2));
        m1 = fmaxf(m1, __shfl_xor_sync(0xffffffffu, m1, 1));
        m1 = fmaxf(m1, __shfl_xor_sync(0xffffffffu, m1, 2));
        if ((lane & 3) == 0) {
            atomicMax(&g_rowmax[q0], enc_f(m0));
            atomicMax(&g_rowmax[q1], enc_f(m1));
        }
    }
}

// ---------------- Phase B: single-pass select + exact softmax + sparse PV --
__global__ __launch_bounds__(256) void sparse_out(const float* __restrict__ X,
                                                  const float* __restrict__ s,
                                                  float* __restrict__ out) {
    __shared__ float s_srow[NDIM];
    __shared__ int   s_idx[MAXSEL];
    __shared__ float s_val[MAXSEL];
    __shared__ int   s_cnt;
    __shared__ float s_bcast;

    const int q = blockIdx.x;
    const int tid = threadIdx.x, lane = tid & 31, wid = tid >> 5;

    // load s[q] into smem (fp32)
    const float4* srow4 = (const float4*)(s + (size_t)q * NDIM);
    for (int i = tid; i < NDIM / 4; i += 256) ((float4*)s_srow)[i] = srow4[i];
    if (tid == 0) s_cnt = 0;
    __syncthreads();

    const float thr = dec_f(g_rowmax[q]) - MARGIN;
    const __half thr_h = __float2half_rd(thr);

    // single selection pass over the S row, 8 halves per uint4 load
    const uint4* Sr4 = (const uint4*)(g_S + (size_t)q * LDS);
    for (int i = tid; i < LDS / 8; i += 256) {
        uint4 v = Sr4[i];
        const __half* h = (const __half*)&v;
#pragma unroll
        for (int e = 0; e < 8; e++) {
            if (__hge(h[e], thr_h)) {
                const int k = i * 8 + e;
                if (k < PQ) {
                    int p = atomicAdd(&s_cnt, 1);
                    if (p < MAXSEL) s_idx[p] = k;
                }
            }
        }
    }
    __syncthreads();
    const int cnt = min(s_cnt, MAXSEL);

    // exact fp32 logits for selected keys: one warp per key
    for (int j = wid; j < cnt; j += 8) {
        const float* xr = X + (size_t)s_idx[j] * NDIM;
        float a = 0.f;
        for (int i = lane; i < NDIM; i += 32) a += s_srow[i] * xr[i];
#pragma unroll
        for (int o = 16; o; o >>= 1) a += __shfl_xor_sync(0xffffffffu, a, o);
        if (lane == 0) s_val[j] = a;
    }
    __syncthreads();

    // softmax over the cnt exact logits (warp 0)
    if (wid == 0) {
        float m = -FLT_MAX;
        for (int j = lane; j < cnt; j += 32) m = fmaxf(m, s_val[j]);
#pragma unroll
        for (int o = 16; o; o >>= 1) m = fmaxf(m, __shfl_xor_sync(0xffffffffu, m, o));
        float sum = 0.f;
        for (int j = lane; j < cnt; j += 32) {
            float e = __expf(s_val[j] - m);
            s_val[j] = e;
            sum += e;
        }
#pragma unroll
        for (int o = 16; o; o >>= 1) sum += __shfl_xor_sync(0xffffffffu, sum, o);
        if (lane == 0) s_bcast = 1.f / sum;
    }
    __syncthreads();
    const float inv = s_bcast;

    // out[q] = sum_j p_j * X[idx_j + 1]; 256 threads x float4
    float4 o = make_float4(0.f, 0.f, 0.f, 0.f);
    for (int j = 0; j < cnt; j++) {
        const float p = s_val[j] * inv;
        const float4 v = ((const float4*)(X + (size_t)(s_idx[j] + 1) * NDIM))[tid];
        o.x += p * v.x; o.y += p * v.y; o.z += p * v.z; o.w += p * v.w;
    }
    ((float4*)(out + (size_t)q * NDIM))[tid] = o;
}

// ---------------- launcher -------------------------------------------------
extern "C" void kernel_launch(void* const* d_in, const int* in_sizes, int n_in,
                              void* d_out, int out_size) {
    const float* X = (const float*)d_in[0];   // (8192, 1024)
    const float* s = (const float*)d_in[1];   // (8191, 1024)
    float* out = (float*)d_out;               // (8191, 1024)

    static bool attr_set = false;
    if (!attr_set) {
        cudaFuncSetAttribute(qk_gemm, cudaFuncAttributeMaxDynamicSharedMemorySize, GSMEM);
        attr_set = true;
    }

    void *p_sh, *p_xh;
    cudaGetSymbolAddress(&p_sh, g_sh);
    cudaGetSymbolAddress(&p_xh, g_xh);

    const size_t NE = (size_t)8192 * 1024;

    init_rowmax<<<LDS / 256, 256>>>();
    cvt_half<<<NE / 256, 256>>>(s, (__half*)p_sh, (size_t)PQ * NDIM);
    cvt_half<<<NE / 256, 256>>>(X, (__half*)p_xh, NE);

    // Phase A: approx logits S = s @ X^T + per-row max epilogue
    qk_gemm<<<dim3(64, 64), 128, GSMEM>>>((const __half*)p_sh, (const __half*)p_xh);

    // Phase B: single-pass select + exact softmax + sparse PV
    sparse_out<<<PQ, 256>>>(X, s, out);
}